// round 7
// baseline (speedup 1.0000x reference)
#include <cuda_runtime.h>
#include <cstdint>

#define N_NODES 50000
#define E_EDGES 800000
#define DIM 128
#define NEG_INF_F __int_as_float(0xff800000)

#define SCAN_B 49          // 49 blocks * 1024 = 50176 >= N_NODES+1
#define SCAN_T 1024
#define HIST_PER_T 16      // 49*1024*16 = 802816 >= E_EDGES

// ---------------------------------------------------------------------------
// Static device scratch. Invariant: g_cnt, g_cur, g_blksum, g_done* are zero
// at entry of every kernel_launch call (zero-init at load; each call restores
// them). Graph-replay deterministic.
// ---------------------------------------------------------------------------
__device__ float g_agg[(size_t)N_NODES * DIM];
__device__ float g_h[(size_t)N_NODES * DIM];
__device__ int   g_is64;                  // 1 if edge_index is int64, else int32
__device__ int   g_cnt[N_NODES];          // per-dst edge counts (restored to 0)
__device__ int   g_row[N_NODES + 1];      // CSR row offsets
__device__ int   g_cur[N_NODES];          // fill cursors (restored to 0)
__device__ int   g_blksum[SCAN_B];        // scan flags: 0=not ready, total+1
__device__ int   g_done1;                 // grid barrier counter (hist->scan)
__device__ int   g_done2;                 // completion counter (reset owner)
__device__ int2  g_edge[E_EDGES];         // {src, bits(weight)} bucketed by dst

// ---------------------------------------------------------------------------
// Kernel 0: fused histogram + exclusive scan (single launch, 49 blocks).
//  Phase A: per-block dtype detect (odd words all-zero iff int64).
//  Phase B: histogram, 16 edges/thread.
//  Grid barrier (49 co-resident blocks, flag+spin).
//  Phase C: cooperative exclusive scan of g_cnt into g_row; zero g_cnt/g_cur.
//  Last block resets barrier state.
// ---------------------------------------------------------------------------
__global__ void __launch_bounds__(SCAN_T, 1)
histscan_kernel(const int* __restrict__ ei32) {
    __shared__ int sh[SCAN_T];
    __shared__ int pre[SCAN_B];
    __shared__ int offset;
    __shared__ int any_nonzero;
    __shared__ int bar_ok;

    int t = threadIdx.x;
    int b = blockIdx.x;

    // --- Phase A: dtype detect (each block independently, same answer) ---
    if (t == 0) any_nonzero = 0;
    __syncthreads();
    if (t < 256) {
        int k = t * 3000;                        // 0 .. 765000 < E_EDGES
        if (ei32[2 * k + 1] != 0) atomicOr(&any_nonzero, 1);
    }
    __syncthreads();
    int is64 = any_nonzero ? 0 : 1;
    if (b == 0 && t == 0) g_is64 = is64;         // for fill_kernel

    // --- Phase B: histogram ---
    const long long* e64 = (const long long*)ei32;
    #pragma unroll
    for (int i = 0; i < HIST_PER_T; ++i) {
        int e = b * SCAN_T + t + i * (SCAN_B * SCAN_T);
        if (e < E_EDGES) {
            int src, dst;
            if (is64) {
                src = (int)e64[e];
                dst = (int)e64[(size_t)E_EDGES + e];
            } else {
                src = ei32[e];
                dst = ei32[(size_t)E_EDGES + e];
            }
            if ((unsigned)src < N_NODES && (unsigned)dst < N_NODES)
                atomicAdd(&g_cnt[dst], 1);
        }
    }

    // --- Grid barrier: all hist atomics visible before scan reads ---
    __threadfence();
    __syncthreads();
    if (t == 0) {
        atomicAdd(&g_done1, 1);
        while (((volatile int*)&g_done1)[0] < SCAN_B) { }
        bar_ok = 1;
    }
    __syncthreads();
    (void)bar_ok;
    __threadfence();

    // --- Phase C: exclusive scan ---
    int idx = b * SCAN_T + t;
    int c = (idx < N_NODES) ? g_cnt[idx] : 0;
    if (idx < N_NODES) g_cnt[idx] = 0;           // restore invariant
    sh[t] = c;
    __syncthreads();
    #pragma unroll
    for (int off = 1; off < SCAN_T; off <<= 1) {
        int v = (t >= off) ? sh[t - off] : 0;
        __syncthreads();
        sh[t] += v;
        __syncthreads();
    }
    int ex = sh[t] - c;                          // local exclusive prefix
    if (t == SCAN_T - 1)
        ((volatile int*)g_blksum)[b] = sh[t] + 1;   // publish total (+1=ready)

    if (t < SCAN_B) {
        int v;
        do { v = ((volatile int*)g_blksum)[t]; } while (v == 0);
        pre[t] = v - 1;
    }
    __syncthreads();
    if (t == 0) {
        int s = 0;
        for (int i = 0; i < b; ++i) s += pre[i];
        offset = s;
    }
    __syncthreads();

    if (idx <= N_NODES) g_row[idx] = ex + offset;
    if (idx < N_NODES)  g_cur[idx] = 0;

    if (t == 0) {
        int old = atomicAdd(&g_done2, 1);
        if (old == SCAN_B - 1) {                 // last block: reset state
            for (int i = 0; i < SCAN_B; ++i) g_blksum[i] = 0;
            g_done1 = 0;
            g_done2 = 0;
        }
    }
}

// ---------------------------------------------------------------------------
// Kernel 1: bucket edges by dst
// ---------------------------------------------------------------------------
__global__ void fill_kernel(const int* __restrict__ ei32,
                            const float* __restrict__ ew) {
    int e = blockIdx.x * blockDim.x + threadIdx.x;
    if (e >= E_EDGES) return;
    int src, dst;
    if (g_is64) {
        const long long* e64 = (const long long*)ei32;
        src = (int)e64[e];
        dst = (int)e64[(size_t)E_EDGES + e];
    } else {
        src = ei32[e];
        dst = ei32[(size_t)E_EDGES + e];
    }
    if ((unsigned)src >= N_NODES || (unsigned)dst >= N_NODES) return;
    int pos = g_row[dst] + atomicAdd(&g_cur[dst], 1);
    g_edge[pos] = make_int2(src, __float_as_int(ew[e]));
}

// ---------------------------------------------------------------------------
// Kernel 2: aggregate. One warp per dst node; lanes cover the 128-dim row
// (float4 each). 8 independent gathers in flight.
// ---------------------------------------------------------------------------
__device__ __forceinline__ float4 max4w(float4 a, float4 v, float w) {
    a.x = fmaxf(a.x, v.x * w);
    a.y = fmaxf(a.y, v.y * w);
    a.z = fmaxf(a.z, v.z * w);
    a.w = fmaxf(a.w, v.w * w);
    return a;
}

__global__ void agg_kernel(const float* __restrict__ x) {
    int warp = (blockIdx.x * blockDim.x + threadIdx.x) >> 5;
    if (warp >= N_NODES) return;
    int lane = threadIdx.x & 31;
    int beg = __ldg(&g_row[warp]);
    int end = __ldg(&g_row[warp + 1]);

    float4 acc = make_float4(NEG_INF_F, NEG_INF_F, NEG_INF_F, NEG_INF_F);
    int j = beg;
    for (; j + 8 <= end; j += 8) {
        int2 e[8];
        #pragma unroll
        for (int i = 0; i < 8; ++i) e[i] = __ldg(&g_edge[j + i]);
        float4 v[8];
        #pragma unroll
        for (int i = 0; i < 8; ++i)
            v[i] = __ldg(&((const float4*)(x + (size_t)e[i].x * DIM))[lane]);
        #pragma unroll
        for (int i = 0; i < 8; ++i)
            acc = max4w(acc, v[i], __int_as_float(e[i].y));
    }
    if (j + 4 <= end) {
        int2 e[4];
        #pragma unroll
        for (int i = 0; i < 4; ++i) e[i] = __ldg(&g_edge[j + i]);
        float4 v[4];
        #pragma unroll
        for (int i = 0; i < 4; ++i)
            v[i] = __ldg(&((const float4*)(x + (size_t)e[i].x * DIM))[lane]);
        #pragma unroll
        for (int i = 0; i < 4; ++i)
            acc = max4w(acc, v[i], __int_as_float(e[i].y));
        j += 4;
    }
    for (; j < end; ++j) {
        int2 ep = __ldg(&g_edge[j]);
        float4 v = __ldg(&((const float4*)(x + (size_t)ep.x * DIM))[lane]);
        acc = max4w(acc, v, __int_as_float(ep.y));
    }
    if (beg == end) acc = make_float4(0.f, 0.f, 0.f, 0.f);
    ((float4*)(g_agg + (size_t)warp * DIM))[lane] = acc;
}

// ---------------------------------------------------------------------------
// Packed fp32x2 helpers (sm_103a FFMA2 — PTX-only)
// ---------------------------------------------------------------------------
__device__ __forceinline__ unsigned long long pack2(float v) {
    unsigned long long r;
    asm("mov.b64 %0, {%1, %1};" : "=l"(r) : "f"(v));
    return r;
}
__device__ __forceinline__ void fma2(unsigned long long& d,
                                     unsigned long long a,
                                     unsigned long long b) {
    asm("fma.rn.f32x2 %0, %1, %2, %0;" : "+l"(d) : "l"(a), "l"(b));
}
__device__ __forceinline__ void unpack2(unsigned long long v, float& lo, float& hi) {
    asm("mov.b64 {%0, %1}, %2;" : "=f"(lo), "=f"(hi) : "l"(v));
}

// ---------------------------------------------------------------------------
// GEMM: OUT[m,o] = act( IN[m,:] @ W[o,:]^T + B[o] )   (unchanged — profiled
// this round at launch index 3)
// ---------------------------------------------------------------------------
#define LDW 132
#define BM  64
#define XS_WORDS (128 * 64)
#define SMEM_BYTES ((128 * LDW + XS_WORDS) * 4)   // 100352 B

template <bool FUSE_INPUT, bool LEAKY>
__global__ void __launch_bounds__(256, 2)
mlp_gemm_kernel(const float* __restrict__ A,
                const float* __restrict__ AGG,
                const float* __restrict__ W,
                const float* __restrict__ B,
                const float* __restrict__ EPS,
                float* __restrict__ OUT) {
    extern __shared__ float sm[];
    float* wT  = sm;                  // [k=128][o] stride LDW
    float* xsT = sm + 128 * LDW;      // swizzled k-major x tile

    const int tid = threadIdx.x;
    const int m0  = blockIdx.x * BM;
    const int tm  = tid >> 4;   // 0..15
    const int tn  = tid & 15;   // 0..15

    float bias[8];
    #pragma unroll
    for (int j = 0; j < 8; ++j) bias[j] = __ldg(&B[tn * 8 + j]);

    for (int idx = tid; idx < 128 * 128; idx += 256) {
        int o = idx >> 7;
        int k = idx & 127;
        wT[k * LDW + o] = W[idx];
    }

    float scale = 1.0f;
    if (FUSE_INPUT) scale = 1.0f + EPS[0];
    #pragma unroll
    for (int p = 0; p < 8; ++p) {
        int r  = p * 8 + (tid >> 5);   // 0..63
        int c4 = tid & 31;             // float4 feature group (k = 4*c4+i)
        int m  = m0 + r;
        float4 v = make_float4(0.f, 0.f, 0.f, 0.f);
        if (m < N_NODES) {
            v = ((const float4*)(A + (size_t)m * DIM))[c4];
            if (FUSE_INPUT) {
                float4 g = ((const float4*)(AGG + (size_t)m * DIM))[c4];
                v.x = scale * v.x + g.x;
                v.y = scale * v.y + g.y;
                v.z = scale * v.z + g.z;
                v.w = scale * v.w + g.w;
            }
        }
        int s = ((((r >> 2) ^ c4) & 15) << 2) + (r & 3);
        xsT[(c4 * 4 + 0) * 64 + s] = v.x;
        xsT[(c4 * 4 + 1) * 64 + s] = v.y;
        xsT[(c4 * 4 + 2) * 64 + s] = v.z;
        xsT[(c4 * 4 + 3) * 64 + s] = v.w;
    }
    __syncthreads();

    unsigned long long acc[4][4];
    #pragma unroll
    for (int i = 0; i < 4; ++i)
        #pragma unroll
        for (int j = 0; j < 4; ++j) acc[i][j] = 0ull;

    const float* bBase = wT + tn * 8;
    const int r0 = tm * 4;

    #pragma unroll 8
    for (int k = 0; k < 128; ++k) {
        float4 av = *(const float4*)(xsT + k * 64 + (((tm ^ (k >> 2)) & 15) << 2));
        ulonglong2 bA = *(const ulonglong2*)(bBase + k * LDW);
        ulonglong2 bB = *(const ulonglong2*)(bBase + k * LDW + 4);
        unsigned long long a0 = pack2(av.x);
        unsigned long long a1 = pack2(av.y);
        unsigned long long a2 = pack2(av.z);
        unsigned long long a3 = pack2(av.w);
        fma2(acc[0][0], a0, bA.x); fma2(acc[0][1], a0, bA.y);
        fma2(acc[0][2], a0, bB.x); fma2(acc[0][3], a0, bB.y);
        fma2(acc[1][0], a1, bA.x); fma2(acc[1][1], a1, bA.y);
        fma2(acc[1][2], a1, bB.x); fma2(acc[1][3], a1, bB.y);
        fma2(acc[2][0], a2, bA.x); fma2(acc[2][1], a2, bA.y);
        fma2(acc[2][2], a2, bB.x); fma2(acc[2][3], a2, bB.y);
        fma2(acc[3][0], a3, bA.x); fma2(acc[3][1], a3, bA.y);
        fma2(acc[3][2], a3, bB.x); fma2(acc[3][3], a3, bB.y);
    }

    #pragma unroll
    for (int i = 0; i < 4; ++i) {
        int m = m0 + r0 + i;
        if (m < N_NODES) {
            float o[8];
            #pragma unroll
            for (int j = 0; j < 4; ++j) unpack2(acc[i][j], o[2 * j], o[2 * j + 1]);
            #pragma unroll
            for (int j = 0; j < 8; ++j) {
                float v = o[j] + bias[j];
                if (LEAKY) v = (v >= 0.0f) ? v : 0.01f * v;
                o[j] = v;
            }
            float4* dst = (float4*)(OUT + (size_t)m * DIM + tn * 8);
            dst[0] = make_float4(o[0], o[1], o[2], o[3]);
            dst[1] = make_float4(o[4], o[5], o[6], o[7]);
        }
    }
}

// ---------------------------------------------------------------------------
// Launcher — order: histscan(0), fill(1), agg(2), gemm1(3) <- ncu, gemm2(4)
// ---------------------------------------------------------------------------
extern "C" void kernel_launch(void* const* d_in, const int* in_sizes, int n_in,
                              void* d_out, int out_size) {
    const float* x   = (const float*)d_in[0];
    const int*   ei  = (const int*)d_in[1];
    const float* ew  = (const float*)d_in[2];
    const float* w1  = (const float*)d_in[3];
    const float* b1  = (const float*)d_in[4];
    const float* w2  = (const float*)d_in[5];
    const float* b2  = (const float*)d_in[6];
    const float* eps = (const float*)d_in[7];
    float*       out = (float*)d_out;

    cudaFuncSetAttribute(mlp_gemm_kernel<true, true>,
                         cudaFuncAttributeMaxDynamicSharedMemorySize, SMEM_BYTES);
    cudaFuncSetAttribute(mlp_gemm_kernel<false, false>,
                         cudaFuncAttributeMaxDynamicSharedMemorySize, SMEM_BYTES);

    void *agg_p = nullptr, *h_p = nullptr;
    cudaGetSymbolAddress(&agg_p, g_agg);
    cudaGetSymbolAddress(&h_p,   g_h);
    float* agg = (float*)agg_p;
    float* h   = (float*)h_p;

    histscan_kernel<<<SCAN_B, SCAN_T>>>(ei);                         // 0
    fill_kernel<<<(E_EDGES + 255) / 256, 256>>>(ei, ew);             // 1
    agg_kernel<<<(N_NODES * 32 + 255) / 256, 256>>>(x);              // 2

    {
        int blocks = (N_NODES + BM - 1) / BM;
        mlp_gemm_kernel<true, true><<<blocks, 256, SMEM_BYTES>>>(    // 3 <- ncu
            x, agg, w1, b1, eps, h);
        mlp_gemm_kernel<false, false><<<blocks, 256, SMEM_BYTES>>>(  // 4
            h, nullptr, w2, b2, eps, out);
    }
}

// round 8
// speedup vs baseline: 1.2215x; 1.2215x over previous
#include <cuda_runtime.h>
#include <cstdint>

#define N_NODES 50000
#define E_EDGES 800000
#define DIM 128
#define NEG_INF_F __int_as_float(0xff800000)

#define SCAN_B 49          // 49 blocks * 1024 = 50176 >= N_NODES+1
#define SCAN_T 1024
#define HIST_PER_T 16      // 49*1024*16 = 802816 >= E_EDGES

// ---------------------------------------------------------------------------
// Static device scratch. Invariant: g_cnt, g_cur, g_blksum, g_done* are zero
// at entry of every kernel_launch call (zero-init at load; each call restores
// them). Graph-replay deterministic.
// ---------------------------------------------------------------------------
__device__ float g_agg[(size_t)N_NODES * DIM];
__device__ float g_h[(size_t)N_NODES * DIM];
__device__ int   g_is64;
__device__ int   g_cnt[N_NODES];
__device__ int   g_row[N_NODES + 1];
__device__ int   g_cur[N_NODES];
__device__ int   g_blksum[SCAN_B];
__device__ int   g_done1;
__device__ int   g_done2;
__device__ int2  g_edge[E_EDGES];

// ---------------------------------------------------------------------------
// Kernel 0: fused histogram + exclusive scan (single launch, 49 blocks).
// ---------------------------------------------------------------------------
__global__ void __launch_bounds__(SCAN_T, 1)
histscan_kernel(const int* __restrict__ ei32) {
    __shared__ int sh[SCAN_T];
    __shared__ int pre[SCAN_B];
    __shared__ int offset;
    __shared__ int any_nonzero;
    __shared__ int bar_ok;

    int t = threadIdx.x;
    int b = blockIdx.x;

    if (t == 0) any_nonzero = 0;
    __syncthreads();
    if (t < 256) {
        int k = t * 3000;
        if (ei32[2 * k + 1] != 0) atomicOr(&any_nonzero, 1);
    }
    __syncthreads();
    int is64 = any_nonzero ? 0 : 1;
    if (b == 0 && t == 0) g_is64 = is64;

    const long long* e64 = (const long long*)ei32;
    #pragma unroll
    for (int i = 0; i < HIST_PER_T; ++i) {
        int e = b * SCAN_T + t + i * (SCAN_B * SCAN_T);
        if (e < E_EDGES) {
            int src, dst;
            if (is64) {
                src = (int)e64[e];
                dst = (int)e64[(size_t)E_EDGES + e];
            } else {
                src = ei32[e];
                dst = ei32[(size_t)E_EDGES + e];
            }
            if ((unsigned)src < N_NODES && (unsigned)dst < N_NODES)
                atomicAdd(&g_cnt[dst], 1);
        }
    }

    __threadfence();
    __syncthreads();
    if (t == 0) {
        atomicAdd(&g_done1, 1);
        while (((volatile int*)&g_done1)[0] < SCAN_B) { }
        bar_ok = 1;
    }
    __syncthreads();
    (void)bar_ok;
    __threadfence();

    int idx = b * SCAN_T + t;
    int c = (idx < N_NODES) ? g_cnt[idx] : 0;
    if (idx < N_NODES) g_cnt[idx] = 0;
    sh[t] = c;
    __syncthreads();
    #pragma unroll
    for (int off = 1; off < SCAN_T; off <<= 1) {
        int v = (t >= off) ? sh[t - off] : 0;
        __syncthreads();
        sh[t] += v;
        __syncthreads();
    }
    int ex = sh[t] - c;
    if (t == SCAN_T - 1)
        ((volatile int*)g_blksum)[b] = sh[t] + 1;

    if (t < SCAN_B) {
        int v;
        do { v = ((volatile int*)g_blksum)[t]; } while (v == 0);
        pre[t] = v - 1;
    }
    __syncthreads();
    if (t == 0) {
        int s = 0;
        for (int i = 0; i < b; ++i) s += pre[i];
        offset = s;
    }
    __syncthreads();

    if (idx <= N_NODES) g_row[idx] = ex + offset;
    if (idx < N_NODES)  g_cur[idx] = 0;

    if (t == 0) {
        int old = atomicAdd(&g_done2, 1);
        if (old == SCAN_B - 1) {
            for (int i = 0; i < SCAN_B; ++i) g_blksum[i] = 0;
            g_done1 = 0;
            g_done2 = 0;
        }
    }
}

// ---------------------------------------------------------------------------
// Kernel 1: bucket edges by dst
// ---------------------------------------------------------------------------
__global__ void fill_kernel(const int* __restrict__ ei32,
                            const float* __restrict__ ew) {
    int e = blockIdx.x * blockDim.x + threadIdx.x;
    if (e >= E_EDGES) return;
    int src, dst;
    if (g_is64) {
        const long long* e64 = (const long long*)ei32;
        src = (int)e64[e];
        dst = (int)e64[(size_t)E_EDGES + e];
    } else {
        src = ei32[e];
        dst = ei32[(size_t)E_EDGES + e];
    }
    if ((unsigned)src >= N_NODES || (unsigned)dst >= N_NODES) return;
    int pos = g_row[dst] + atomicAdd(&g_cur[dst], 1);
    g_edge[pos] = make_int2(src, __float_as_int(ew[e]));
}

// ---------------------------------------------------------------------------
// Kernel 2: aggregate. One warp per dst node.
// ---------------------------------------------------------------------------
__device__ __forceinline__ float4 max4w(float4 a, float4 v, float w) {
    a.x = fmaxf(a.x, v.x * w);
    a.y = fmaxf(a.y, v.y * w);
    a.z = fmaxf(a.z, v.z * w);
    a.w = fmaxf(a.w, v.w * w);
    return a;
}

__global__ void agg_kernel(const float* __restrict__ x) {
    int warp = (blockIdx.x * blockDim.x + threadIdx.x) >> 5;
    if (warp >= N_NODES) return;
    int lane = threadIdx.x & 31;
    int beg = __ldg(&g_row[warp]);
    int end = __ldg(&g_row[warp + 1]);

    float4 acc = make_float4(NEG_INF_F, NEG_INF_F, NEG_INF_F, NEG_INF_F);
    int j = beg;
    for (; j + 8 <= end; j += 8) {
        int2 e[8];
        #pragma unroll
        for (int i = 0; i < 8; ++i) e[i] = __ldg(&g_edge[j + i]);
        float4 v[8];
        #pragma unroll
        for (int i = 0; i < 8; ++i)
            v[i] = __ldg(&((const float4*)(x + (size_t)e[i].x * DIM))[lane]);
        #pragma unroll
        for (int i = 0; i < 8; ++i)
            acc = max4w(acc, v[i], __int_as_float(e[i].y));
    }
    if (j + 4 <= end) {
        int2 e[4];
        #pragma unroll
        for (int i = 0; i < 4; ++i) e[i] = __ldg(&g_edge[j + i]);
        float4 v[4];
        #pragma unroll
        for (int i = 0; i < 4; ++i)
            v[i] = __ldg(&((const float4*)(x + (size_t)e[i].x * DIM))[lane]);
        #pragma unroll
        for (int i = 0; i < 4; ++i)
            acc = max4w(acc, v[i], __int_as_float(e[i].y));
        j += 4;
    }
    for (; j < end; ++j) {
        int2 ep = __ldg(&g_edge[j]);
        float4 v = __ldg(&((const float4*)(x + (size_t)ep.x * DIM))[lane]);
        acc = max4w(acc, v, __int_as_float(ep.y));
    }
    if (beg == end) acc = make_float4(0.f, 0.f, 0.f, 0.f);
    ((float4*)(g_agg + (size_t)warp * DIM))[lane] = acc;
}

// ---------------------------------------------------------------------------
// Packed fp32x2 helpers (sm_103a FFMA2 — PTX-only)
// ---------------------------------------------------------------------------
__device__ __forceinline__ unsigned long long pack2(float v) {
    unsigned long long r;
    asm("mov.b64 %0, {%1, %1};" : "=l"(r) : "f"(v));
    return r;
}
__device__ __forceinline__ void fma2(unsigned long long& d,
                                     unsigned long long a,
                                     unsigned long long b) {
    asm("fma.rn.f32x2 %0, %1, %2, %0;" : "+l"(d) : "l"(a), "l"(b));
}
__device__ __forceinline__ void unpack2(unsigned long long v, float& lo, float& hi) {
    asm("mov.b64 {%0, %1}, %2;" : "=f"(lo), "=f"(hi) : "l"(v));
}

// ---------------------------------------------------------------------------
// GEMM: OUT[m,o] = act( IN[m,:] @ W[o,:]^T + B[o] )
// BM=128 x BN=128, 256 threads, 8x8 thread tile (64 outputs, 32 f32x2 accs).
// W transposed in smem (LDW=132, 16B-aligned rows). x tile ROW-major [r][k]
// (128 words/row): staging stores are contiguous float4 (bandwidth-optimal),
// A mainloop loads are LDS.128 along k with 2-address broadcast per instr.
// Per 4-k chunk per thread: 16 LDS.128 vs 128 FFMA2 -> FMA-bound.
// 1 CTA/SM (133,120 B smem).
// ---------------------------------------------------------------------------
#define LDW 132
#define BMG 128
#define SMEM_BYTES ((128 * LDW + 128 * 128) * 4)   // 67584 + 65536 = 133120 B

template <bool FUSE_INPUT, bool LEAKY>
__global__ void __launch_bounds__(256)
mlp_gemm_kernel(const float* __restrict__ A,
                const float* __restrict__ AGG,
                const float* __restrict__ W,
                const float* __restrict__ B,
                const float* __restrict__ EPS,
                float* __restrict__ OUT) {
    extern __shared__ float sm[];
    float* wT = sm;                   // [k=128][o] stride LDW
    float* xs = sm + 128 * LDW;       // [r=128][k=128] row-major

    const int tid = threadIdx.x;
    const int m0  = blockIdx.x * BMG;
    const int tm  = tid >> 4;   // 0..15 -> rows tm*8 .. tm*8+7
    const int tn  = tid & 15;   // 0..15 -> cols tn*8 .. tn*8+7

    float bias[8];
    #pragma unroll
    for (int j = 0; j < 8; ++j) bias[j] = __ldg(&B[tn * 8 + j]);

    // Stage W transposed: wT[k][o] = W[o*128 + k]
    for (int idx = tid; idx < 128 * 128; idx += 256) {
        int o = idx >> 7;
        int k = idx & 127;
        wT[k * LDW + o] = W[idx];
    }

    // Stage input tile row-major (optionally fused with agg/eps)
    float scale = 1.0f;
    if (FUSE_INPUT) scale = 1.0f + EPS[0];
    #pragma unroll
    for (int p = 0; p < 16; ++p) {
        int r  = p * 8 + (tid >> 5);   // 0..127
        int c4 = tid & 31;             // float4 feature group
        int m  = m0 + r;
        float4 v = make_float4(0.f, 0.f, 0.f, 0.f);
        if (m < N_NODES) {
            v = ((const float4*)(A + (size_t)m * DIM))[c4];
            if (FUSE_INPUT) {
                float4 g = ((const float4*)(AGG + (size_t)m * DIM))[c4];
                v.x = scale * v.x + g.x;
                v.y = scale * v.y + g.y;
                v.z = scale * v.z + g.z;
                v.w = scale * v.w + g.w;
            }
        }
        *(float4*)(xs + r * 128 + c4 * 4) = v;
    }
    __syncthreads();

    unsigned long long acc[8][4];
    #pragma unroll
    for (int i = 0; i < 8; ++i)
        #pragma unroll
        for (int j = 0; j < 4; ++j) acc[i][j] = 0ull;

    const float* aBase = xs + (tm * 8) * 128;
    const float* bBase = wT + tn * 8;

    #pragma unroll 2
    for (int kc = 0; kc < 32; ++kc) {
        // A: 8 rows x 4 consecutive k each (one LDS.128 per row)
        float4 a[8];
        #pragma unroll
        for (int i = 0; i < 8; ++i)
            a[i] = *(const float4*)(aBase + i * 128 + kc * 4);

        #pragma unroll
        for (int q = 0; q < 4; ++q) {
            int k = kc * 4 + q;
            ulonglong2 bA = *(const ulonglong2*)(bBase + k * LDW);
            ulonglong2 bB = *(const ulonglong2*)(bBase + k * LDW + 4);
            #pragma unroll
            for (int i = 0; i < 8; ++i) {
                const float* af = (const float*)&a[i];
                unsigned long long ai = pack2(af[q]);
                fma2(acc[i][0], ai, bA.x);
                fma2(acc[i][1], ai, bA.y);
                fma2(acc[i][2], ai, bB.x);
                fma2(acc[i][3], ai, bB.y);
            }
        }
    }

    // Epilogue: bias (+LeakyReLU) and store
    #pragma unroll
    for (int i = 0; i < 8; ++i) {
        int m = m0 + tm * 8 + i;
        if (m < N_NODES) {
            float o[8];
            #pragma unroll
            for (int j = 0; j < 4; ++j) unpack2(acc[i][j], o[2 * j], o[2 * j + 1]);
            #pragma unroll
            for (int j = 0; j < 8; ++j) {
                float v = o[j] + bias[j];
                if (LEAKY) v = (v >= 0.0f) ? v : 0.01f * v;
                o[j] = v;
            }
            float4* dst = (float4*)(OUT + (size_t)m * DIM + tn * 8);
            dst[0] = make_float4(o[0], o[1], o[2], o[3]);
            dst[1] = make_float4(o[4], o[5], o[6], o[7]);
        }
    }
}

// ---------------------------------------------------------------------------
// Launcher — order: histscan(0), fill(1), agg(2), gemm1(3) <- ncu, gemm2(4)
// ---------------------------------------------------------------------------
extern "C" void kernel_launch(void* const* d_in, const int* in_sizes, int n_in,
                              void* d_out, int out_size) {
    const float* x   = (const float*)d_in[0];
    const int*   ei  = (const int*)d_in[1];
    const float* ew  = (const float*)d_in[2];
    const float* w1  = (const float*)d_in[3];
    const float* b1  = (const float*)d_in[4];
    const float* w2  = (const float*)d_in[5];
    const float* b2  = (const float*)d_in[6];
    const float* eps = (const float*)d_in[7];
    float*       out = (float*)d_out;

    cudaFuncSetAttribute(mlp_gemm_kernel<true, true>,
                         cudaFuncAttributeMaxDynamicSharedMemorySize, SMEM_BYTES);
    cudaFuncSetAttribute(mlp_gemm_kernel<false, false>,
                         cudaFuncAttributeMaxDynamicSharedMemorySize, SMEM_BYTES);

    void *agg_p = nullptr, *h_p = nullptr;
    cudaGetSymbolAddress(&agg_p, g_agg);
    cudaGetSymbolAddress(&h_p,   g_h);
    float* agg = (float*)agg_p;
    float* h   = (float*)h_p;

    histscan_kernel<<<SCAN_B, SCAN_T>>>(ei);                         // 0
    fill_kernel<<<(E_EDGES + 255) / 256, 256>>>(ei, ew);             // 1
    agg_kernel<<<(N_NODES * 32 + 255) / 256, 256>>>(x);              // 2

    {
        int blocks = (N_NODES + BMG - 1) / BMG;
        mlp_gemm_kernel<true, true><<<blocks, 256, SMEM_BYTES>>>(    // 3 <- ncu
            x, agg, w1, b1, eps, h);
        mlp_gemm_kernel<false, false><<<blocks, 256, SMEM_BYTES>>>(  // 4
            h, nullptr, w2, b2, eps, out);
    }
}

// round 9
// speedup vs baseline: 1.3617x; 1.1148x over previous
#include <cuda_runtime.h>
#include <cstdint>

#define N_NODES 50000
#define E_EDGES 800000
#define DIM 128
#define NEG_INF_F __int_as_float(0xff800000)

#define SCAN_B 49          // 49 blocks * 1024 = 50176 >= N_NODES+1
#define SCAN_T 1024
#define HIST_PER_T 16      // 49*1024*16 = 802816 >= E_EDGES

// ---------------------------------------------------------------------------
// Static device scratch. Invariant: g_cnt, g_cur, g_blksum, g_done* are zero
// at entry of every kernel_launch call (zero-init at load; each call restores
// them). Graph-replay deterministic.
// ---------------------------------------------------------------------------
__device__ float g_agg[(size_t)N_NODES * DIM];
__device__ float g_h[(size_t)N_NODES * DIM];
__device__ int   g_is64;
__device__ int   g_cnt[N_NODES];
__device__ int   g_row[N_NODES + 1];
__device__ int   g_cur[N_NODES];
__device__ int   g_blksum[SCAN_B];
__device__ int   g_done1;
__device__ int   g_done2;
__device__ int2  g_edge[E_EDGES];

// ---------------------------------------------------------------------------
// Kernel 0: fused histogram + exclusive scan (single launch, 49 blocks).
// ---------------------------------------------------------------------------
__global__ void __launch_bounds__(SCAN_T, 1)
histscan_kernel(const int* __restrict__ ei32) {
    __shared__ int sh[SCAN_T];
    __shared__ int pre[SCAN_B];
    __shared__ int offset;
    __shared__ int any_nonzero;
    __shared__ int bar_ok;

    int t = threadIdx.x;
    int b = blockIdx.x;

    if (t == 0) any_nonzero = 0;
    __syncthreads();
    if (t < 256) {
        int k = t * 3000;
        if (ei32[2 * k + 1] != 0) atomicOr(&any_nonzero, 1);
    }
    __syncthreads();
    int is64 = any_nonzero ? 0 : 1;
    if (b == 0 && t == 0) g_is64 = is64;

    const long long* e64 = (const long long*)ei32;
    #pragma unroll
    for (int i = 0; i < HIST_PER_T; ++i) {
        int e = b * SCAN_T + t + i * (SCAN_B * SCAN_T);
        if (e < E_EDGES) {
            int src, dst;
            if (is64) {
                src = (int)e64[e];
                dst = (int)e64[(size_t)E_EDGES + e];
            } else {
                src = ei32[e];
                dst = ei32[(size_t)E_EDGES + e];
            }
            if ((unsigned)src < N_NODES && (unsigned)dst < N_NODES)
                atomicAdd(&g_cnt[dst], 1);
        }
    }

    __threadfence();
    __syncthreads();
    if (t == 0) {
        atomicAdd(&g_done1, 1);
        while (((volatile int*)&g_done1)[0] < SCAN_B) { }
        bar_ok = 1;
    }
    __syncthreads();
    (void)bar_ok;
    __threadfence();

    int idx = b * SCAN_T + t;
    int c = (idx < N_NODES) ? g_cnt[idx] : 0;
    if (idx < N_NODES) g_cnt[idx] = 0;
    sh[t] = c;
    __syncthreads();
    #pragma unroll
    for (int off = 1; off < SCAN_T; off <<= 1) {
        int v = (t >= off) ? sh[t - off] : 0;
        __syncthreads();
        sh[t] += v;
        __syncthreads();
    }
    int ex = sh[t] - c;
    if (t == SCAN_T - 1)
        ((volatile int*)g_blksum)[b] = sh[t] + 1;

    if (t < SCAN_B) {
        int v;
        do { v = ((volatile int*)g_blksum)[t]; } while (v == 0);
        pre[t] = v - 1;
    }
    __syncthreads();
    if (t == 0) {
        int s = 0;
        for (int i = 0; i < b; ++i) s += pre[i];
        offset = s;
    }
    __syncthreads();

    if (idx <= N_NODES) g_row[idx] = ex + offset;
    if (idx < N_NODES)  g_cur[idx] = 0;

    if (t == 0) {
        int old = atomicAdd(&g_done2, 1);
        if (old == SCAN_B - 1) {
            for (int i = 0; i < SCAN_B; ++i) g_blksum[i] = 0;
            g_done1 = 0;
            g_done2 = 0;
        }
    }
}

// ---------------------------------------------------------------------------
// Kernel 1: bucket edges by dst
// ---------------------------------------------------------------------------
__global__ void fill_kernel(const int* __restrict__ ei32,
                            const float* __restrict__ ew) {
    int e = blockIdx.x * blockDim.x + threadIdx.x;
    if (e >= E_EDGES) return;
    int src, dst;
    if (g_is64) {
        const long long* e64 = (const long long*)ei32;
        src = (int)e64[e];
        dst = (int)e64[(size_t)E_EDGES + e];
    } else {
        src = ei32[e];
        dst = ei32[(size_t)E_EDGES + e];
    }
    if ((unsigned)src >= N_NODES || (unsigned)dst >= N_NODES) return;
    int pos = g_row[dst] + atomicAdd(&g_cur[dst], 1);
    g_edge[pos] = make_int2(src, __float_as_int(ew[e]));
}

// ---------------------------------------------------------------------------
// Kernel 2: aggregate. One warp per dst node.
// ---------------------------------------------------------------------------
__device__ __forceinline__ float4 max4w(float4 a, float4 v, float w) {
    a.x = fmaxf(a.x, v.x * w);
    a.y = fmaxf(a.y, v.y * w);
    a.z = fmaxf(a.z, v.z * w);
    a.w = fmaxf(a.w, v.w * w);
    return a;
}

__global__ void agg_kernel(const float* __restrict__ x) {
    int warp = (blockIdx.x * blockDim.x + threadIdx.x) >> 5;
    if (warp >= N_NODES) return;
    int lane = threadIdx.x & 31;
    int beg = __ldg(&g_row[warp]);
    int end = __ldg(&g_row[warp + 1]);

    float4 acc = make_float4(NEG_INF_F, NEG_INF_F, NEG_INF_F, NEG_INF_F);
    int j = beg;
    for (; j + 8 <= end; j += 8) {
        int2 e[8];
        #pragma unroll
        for (int i = 0; i < 8; ++i) e[i] = __ldg(&g_edge[j + i]);
        float4 v[8];
        #pragma unroll
        for (int i = 0; i < 8; ++i)
            v[i] = __ldg(&((const float4*)(x + (size_t)e[i].x * DIM))[lane]);
        #pragma unroll
        for (int i = 0; i < 8; ++i)
            acc = max4w(acc, v[i], __int_as_float(e[i].y));
    }
    if (j + 4 <= end) {
        int2 e[4];
        #pragma unroll
        for (int i = 0; i < 4; ++i) e[i] = __ldg(&g_edge[j + i]);
        float4 v[4];
        #pragma unroll
        for (int i = 0; i < 4; ++i)
            v[i] = __ldg(&((const float4*)(x + (size_t)e[i].x * DIM))[lane]);
        #pragma unroll
        for (int i = 0; i < 4; ++i)
            acc = max4w(acc, v[i], __int_as_float(e[i].y));
        j += 4;
    }
    for (; j < end; ++j) {
        int2 ep = __ldg(&g_edge[j]);
        float4 v = __ldg(&((const float4*)(x + (size_t)ep.x * DIM))[lane]);
        acc = max4w(acc, v, __int_as_float(ep.y));
    }
    if (beg == end) acc = make_float4(0.f, 0.f, 0.f, 0.f);
    ((float4*)(g_agg + (size_t)warp * DIM))[lane] = acc;
}

// ---------------------------------------------------------------------------
// Packed fp32x2 helpers (sm_103a FFMA2 — PTX-only)
// ---------------------------------------------------------------------------
__device__ __forceinline__ unsigned long long pack2(float v) {
    unsigned long long r;
    asm("mov.b64 %0, {%1, %1};" : "=l"(r) : "f"(v));
    return r;
}
__device__ __forceinline__ void fma2(unsigned long long& d,
                                     unsigned long long a,
                                     unsigned long long b) {
    asm("fma.rn.f32x2 %0, %1, %2, %0;" : "+l"(d) : "l"(a), "l"(b));
}
__device__ __forceinline__ void unpack2(unsigned long long v, float& lo, float& hi) {
    asm("mov.b64 {%0, %1}, %2;" : "=f"(lo), "=f"(hi) : "l"(v));
}

// ---------------------------------------------------------------------------
// GEMM: OUT[m,o] = act( IN[m,:] @ W[o,:]^T + B[o] )
// BM=128 x BN=128, 512 threads (16 warps, occ 25%), thread tile 4 rows x
// 8 cols SPLIT as {tn*4..+3} and {64+tn*4..+3} -> B LDS.128 addresses stride
// 16B (2-phase) instead of 32B (4-phase).
// W transposed in smem (LDW=132). x tile row-major [r][k] (contiguous float4
// staging; A mainloop loads LDS.128 along k, 2 addrs/warp broadcast).
// 1 CTA/SM (133,120 B smem).
// ---------------------------------------------------------------------------
#define LDW 132
#define BMG 128
#define GEMM_T 512
#define SMEM_BYTES ((128 * LDW + 128 * 128) * 4)   // 67584 + 65536 = 133120 B

template <bool FUSE_INPUT, bool LEAKY>
__global__ void __launch_bounds__(GEMM_T)
mlp_gemm_kernel(const float* __restrict__ A,
                const float* __restrict__ AGG,
                const float* __restrict__ W,
                const float* __restrict__ B,
                const float* __restrict__ EPS,
                float* __restrict__ OUT) {
    extern __shared__ float sm[];
    float* wT = sm;                   // [k=128][o] stride LDW
    float* xs = sm + 128 * LDW;       // [r=128][k=128] row-major

    const int tid = threadIdx.x;
    const int m0  = blockIdx.x * BMG;
    const int tm  = tid >> 4;   // 0..31 -> rows tm*4 .. tm*4+3
    const int tn  = tid & 15;   // 0..15 -> cols tn*4..+3 and 64+tn*4..+3

    float bias[8];
    #pragma unroll
    for (int j = 0; j < 4; ++j) {
        bias[j]     = __ldg(&B[tn * 4 + j]);
        bias[4 + j] = __ldg(&B[64 + tn * 4 + j]);
    }

    // Stage W transposed: wT[k][o] = W[o*128 + k]
    for (int idx = tid; idx < 128 * 128; idx += GEMM_T) {
        int o = idx >> 7;
        int k = idx & 127;
        wT[k * LDW + o] = W[idx];
    }

    // Stage input tile row-major (optionally fused with agg/eps)
    float scale = 1.0f;
    if (FUSE_INPUT) scale = 1.0f + EPS[0];
    #pragma unroll
    for (int p = 0; p < 8; ++p) {
        int r  = p * 16 + (tid >> 5);  // 0..127
        int c4 = tid & 31;             // float4 feature group
        int m  = m0 + r;
        float4 v = make_float4(0.f, 0.f, 0.f, 0.f);
        if (m < N_NODES) {
            v = ((const float4*)(A + (size_t)m * DIM))[c4];
            if (FUSE_INPUT) {
                float4 g = ((const float4*)(AGG + (size_t)m * DIM))[c4];
                v.x = scale * v.x + g.x;
                v.y = scale * v.y + g.y;
                v.z = scale * v.z + g.z;
                v.w = scale * v.w + g.w;
            }
        }
        *(float4*)(xs + r * 128 + c4 * 4) = v;
    }
    __syncthreads();

    unsigned long long acc[4][4];
    #pragma unroll
    for (int i = 0; i < 4; ++i)
        #pragma unroll
        for (int j = 0; j < 4; ++j) acc[i][j] = 0ull;

    const float* aBase = xs + (tm * 4) * 128;
    const float* bBase = wT + tn * 4;

    #pragma unroll 4
    for (int kc = 0; kc < 32; ++kc) {
        // A: 4 rows x 4 consecutive k each (one LDS.128 per row)
        float4 a[4];
        #pragma unroll
        for (int i = 0; i < 4; ++i)
            a[i] = *(const float4*)(aBase + i * 128 + kc * 4);

        #pragma unroll
        for (int q = 0; q < 4; ++q) {
            int k = kc * 4 + q;
            ulonglong2 bA = *(const ulonglong2*)(bBase + k * LDW);        // cols tn*4..+3
            ulonglong2 bB = *(const ulonglong2*)(bBase + k * LDW + 64);   // cols 64+tn*4..+3
            const float* af0 = (const float*)&a[0];
            const float* af1 = (const float*)&a[1];
            const float* af2 = (const float*)&a[2];
            const float* af3 = (const float*)&a[3];
            unsigned long long a0 = pack2(af0[q]);
            unsigned long long a1 = pack2(af1[q]);
            unsigned long long a2 = pack2(af2[q]);
            unsigned long long a3 = pack2(af3[q]);
            fma2(acc[0][0], a0, bA.x); fma2(acc[0][1], a0, bA.y);
            fma2(acc[0][2], a0, bB.x); fma2(acc[0][3], a0, bB.y);
            fma2(acc[1][0], a1, bA.x); fma2(acc[1][1], a1, bA.y);
            fma2(acc[1][2], a1, bB.x); fma2(acc[1][3], a1, bB.y);
            fma2(acc[2][0], a2, bA.x); fma2(acc[2][1], a2, bA.y);
            fma2(acc[2][2], a2, bB.x); fma2(acc[2][3], a2, bB.y);
            fma2(acc[3][0], a3, bA.x); fma2(acc[3][1], a3, bA.y);
            fma2(acc[3][2], a3, bB.x); fma2(acc[3][3], a3, bB.y);
        }
    }

    // Epilogue: bias (+LeakyReLU) and store (two float4 per row)
    #pragma unroll
    for (int i = 0; i < 4; ++i) {
        int m = m0 + tm * 4 + i;
        if (m < N_NODES) {
            float o[8];
            unpack2(acc[i][0], o[0], o[1]);
            unpack2(acc[i][1], o[2], o[3]);
            unpack2(acc[i][2], o[4], o[5]);
            unpack2(acc[i][3], o[6], o[7]);
            #pragma unroll
            for (int j = 0; j < 8; ++j) {
                float v = o[j] + bias[j];
                if (LEAKY) v = (v >= 0.0f) ? v : 0.01f * v;
                o[j] = v;
            }
            *(float4*)(OUT + (size_t)m * DIM + tn * 4)      = make_float4(o[0], o[1], o[2], o[3]);
            *(float4*)(OUT + (size_t)m * DIM + 64 + tn * 4) = make_float4(o[4], o[5], o[6], o[7]);
        }
    }
}

// ---------------------------------------------------------------------------
// Launcher — order: histscan(0), fill(1), agg(2), gemm1(3) <- ncu, gemm2(4)
// ---------------------------------------------------------------------------
extern "C" void kernel_launch(void* const* d_in, const int* in_sizes, int n_in,
                              void* d_out, int out_size) {
    const float* x   = (const float*)d_in[0];
    const int*   ei  = (const int*)d_in[1];
    const float* ew  = (const float*)d_in[2];
    const float* w1  = (const float*)d_in[3];
    const float* b1  = (const float*)d_in[4];
    const float* w2  = (const float*)d_in[5];
    const float* b2  = (const float*)d_in[6];
    const float* eps = (const float*)d_in[7];
    float*       out = (float*)d_out;

    cudaFuncSetAttribute(mlp_gemm_kernel<true, true>,
                         cudaFuncAttributeMaxDynamicSharedMemorySize, SMEM_BYTES);
    cudaFuncSetAttribute(mlp_gemm_kernel<false, false>,
                         cudaFuncAttributeMaxDynamicSharedMemorySize, SMEM_BYTES);

    void *agg_p = nullptr, *h_p = nullptr;
    cudaGetSymbolAddress(&agg_p, g_agg);
    cudaGetSymbolAddress(&h_p,   g_h);
    float* agg = (float*)agg_p;
    float* h   = (float*)h_p;

    histscan_kernel<<<SCAN_B, SCAN_T>>>(ei);                         // 0
    fill_kernel<<<(E_EDGES + 255) / 256, 256>>>(ei, ew);             // 1
    agg_kernel<<<(N_NODES * 32 + 255) / 256, 256>>>(x);              // 2

    {
        int blocks = (N_NODES + BMG - 1) / BMG;
        mlp_gemm_kernel<true, true><<<blocks, GEMM_T, SMEM_BYTES>>>(   // 3 <- ncu
            x, agg, w1, b1, eps, h);
        mlp_gemm_kernel<false, false><<<blocks, GEMM_T, SMEM_BYTES>>>( // 4
            h, nullptr, w2, b2, eps, out);
    }
}